// round 15
// baseline (speedup 1.0000x reference)
#include <cuda_runtime.h>
#include <cuda_fp16.h>
#include <cstdint>
#include <cstddef>

// Problem constants
#define BATCH 2
#define NSEQ 4096
#define CDIM 512
#define C3   1536
#define NH   8
#define HD   64
#define NROWS (BATCH*NSEQ)      // 8192
#define QK_LOG2_SCALE (0.125f * 1.44269504f)

// Scratch (allocation-free rule: device globals)
__device__ float  g_xn  [(size_t)NROWS * CDIM];  // fp32 pre-norm (residual)
__device__ __half g_xnh [(size_t)NROWS * CDIM];  // fp16 pre-norm (GEMM A)
__device__ __half g_wh  [(size_t)CDIM * C3];     // fp16 W
__device__ __half g_qkvh[(size_t)NROWS * C3];    // fp16 qkv (Q pre-scaled)
__device__ float  g_val [(size_t)NROWS * CDIM];  // attention output

static __device__ __forceinline__ uint32_t pack_f16(float lo, float hi) {
    __half2 p = __floats2half2_rn(lo, hi);
    return *(uint32_t*)&p;
}
// fp32-accumulator fp16 mma
static __device__ __forceinline__ void mma_f16(float* c, const uint32_t* a,
                                               uint32_t b0, uint32_t b1) {
    asm volatile(
        "mma.sync.aligned.m16n8k16.row.col.f32.f16.f16.f32 "
        "{%0,%1,%2,%3},{%4,%5,%6,%7},{%8,%9},{%0,%1,%2,%3};"
        : "+f"(c[0]), "+f"(c[1]), "+f"(c[2]), "+f"(c[3])
        : "r"(a[0]), "r"(a[1]), "r"(a[2]), "r"(a[3]), "r"(b0), "r"(b1));
}
// fp16-accumulator fp16 mma (2 packed f16x2 accumulator regs)
static __device__ __forceinline__ void mma_f16_h(uint32_t* c, const uint32_t* a,
                                                 uint32_t b0, uint32_t b1) {
    asm volatile(
        "mma.sync.aligned.m16n8k16.row.col.f16.f16.f16.f16 "
        "{%0,%1},{%2,%3,%4,%5},{%6,%7},{%0,%1};"
        : "+r"(c[0]), "+r"(c[1])
        : "r"(a[0]), "r"(a[1]), "r"(a[2]), "r"(a[3]), "r"(b0), "r"(b1));
}
// packed fp16x2 exp2 (MUFU, one instr for two exps; output stays fp16)
#define H2EXP2(d, s) asm("ex2.approx.f16x2 %0, %1;" : "=r"(d) : "r"(s))
// packed fp16x2 add (accumulate P fragments for row sums)
#define HADD2(acc, v) asm("add.rn.f16x2 %0, %0, %1;" : "+r"(acc) : "r"(v))

static __device__ __forceinline__ void ldmatrix_x4(uint32_t& r0, uint32_t& r1,
                                                   uint32_t& r2, uint32_t& r3,
                                                   const void* p) {
    uint32_t addr = (uint32_t)__cvta_generic_to_shared(p);
    asm volatile("ldmatrix.sync.aligned.m8n8.x4.shared.b16 {%0,%1,%2,%3}, [%4];"
                 : "=r"(r0), "=r"(r1), "=r"(r2), "=r"(r3) : "r"(addr));
}
static __device__ __forceinline__ void ldmatrix_x4_trans(uint32_t& r0, uint32_t& r1,
                                                         uint32_t& r2, uint32_t& r3,
                                                         const void* p) {
    uint32_t addr = (uint32_t)__cvta_generic_to_shared(p);
    asm volatile("ldmatrix.sync.aligned.m8n8.x4.trans.shared.b16 {%0,%1,%2,%3}, [%4];"
                 : "=r"(r0), "=r"(r1), "=r"(r2), "=r"(r3) : "r"(addr));
}
static __device__ __forceinline__ void cp16(uint32_t dst, const void* src) {
    asm volatile("cp.async.cg.shared.global [%0], [%1], 16;" :: "r"(dst), "l"(src) : "memory");
}
#define CP_COMMIT() asm volatile("cp.async.commit_group;" ::: "memory")
#define CP_WAIT1()  asm volatile("cp.async.wait_group 1;" ::: "memory")
#define CP_WAIT0()  asm volatile("cp.async.wait_group 0;" ::: "memory")

// ---------------------------------------------------------------------------
// Pre-LayerNorm (fp32), 2 rows per warp (interleaved loads for MLP=8);
// emits fp32 + fp16 copies.  Grid: NROWS/16 blocks x 256 threads.
// ---------------------------------------------------------------------------
__global__ void pre_ln_kernel(const float* __restrict__ x,
                              const float* __restrict__ g,
                              const float* __restrict__ beta) {
    int wid = threadIdx.x >> 5, lane = threadIdx.x & 31;
    int rowa = blockIdx.x * 16 + wid * 2;
    int rowb = rowa + 1;
    const float* xa = x + (size_t)rowa * CDIM;
    const float* xb = x + (size_t)rowb * CDIM;
    float4 va[4], vb[4];
    #pragma unroll
    for (int i = 0; i < 4; i++) {
        va[i] = *(const float4*)(xa + (lane + i * 32) * 4);
        vb[i] = *(const float4*)(xb + (lane + i * 32) * 4);
    }
    float sa = 0.f, sa2 = 0.f, sb = 0.f, sb2 = 0.f;
    #pragma unroll
    for (int i = 0; i < 4; i++) {
        sa  += (va[i].x + va[i].y) + (va[i].z + va[i].w);
        sa2 += (va[i].x * va[i].x + va[i].y * va[i].y) + (va[i].z * va[i].z + va[i].w * va[i].w);
        sb  += (vb[i].x + vb[i].y) + (vb[i].z + vb[i].w);
        sb2 += (vb[i].x * vb[i].x + vb[i].y * vb[i].y) + (vb[i].z * vb[i].z + vb[i].w * vb[i].w);
    }
    #pragma unroll
    for (int o = 16; o > 0; o >>= 1) {
        sa  += __shfl_xor_sync(0xffffffffu, sa,  o);
        sa2 += __shfl_xor_sync(0xffffffffu, sa2, o);
        sb  += __shfl_xor_sync(0xffffffffu, sb,  o);
        sb2 += __shfl_xor_sync(0xffffffffu, sb2, o);
    }
    float ma = sa * (1.f / CDIM), mb = sb * (1.f / CDIM);
    float ra = rsqrtf(sa2 * (1.f / CDIM) - ma * ma + 1e-5f);
    float rb = rsqrtf(sb2 * (1.f / CDIM) - mb * mb + 1e-5f);
    float*  oa = g_xn  + (size_t)rowa * CDIM;
    float*  ob = g_xn  + (size_t)rowb * CDIM;
    __half* ha = g_xnh + (size_t)rowa * CDIM;
    __half* hb = g_xnh + (size_t)rowb * CDIM;
    #pragma unroll
    for (int i = 0; i < 4; i++) {
        int idx = (lane + i * 32) * 4;
        float4 gv = *(const float4*)(g + idx);
        float4 bv = *(const float4*)(beta + idx);
        float4 o1, o2;
        o1.x = (va[i].x - ma) * ra * gv.x + bv.x;
        o1.y = (va[i].y - ma) * ra * gv.y + bv.y;
        o1.z = (va[i].z - ma) * ra * gv.z + bv.z;
        o1.w = (va[i].w - ma) * ra * gv.w + bv.w;
        o2.x = (vb[i].x - mb) * rb * gv.x + bv.x;
        o2.y = (vb[i].y - mb) * rb * gv.y + bv.y;
        o2.z = (vb[i].z - mb) * rb * gv.z + bv.z;
        o2.w = (vb[i].w - mb) * rb * gv.w + bv.w;
        *(float4*)(oa + idx) = o1;
        *(float4*)(ob + idx) = o2;
        uint2 p1, p2;
        p1.x = pack_f16(o1.x, o1.y); p1.y = pack_f16(o1.z, o1.w);
        p2.x = pack_f16(o2.x, o2.y); p2.y = pack_f16(o2.z, o2.w);
        *(uint2*)(ha + idx) = p1;
        *(uint2*)(hb + idx) = p2;
    }
}

// ---------------------------------------------------------------------------
// W fp32 -> fp16 conversion (once per launch).
// ---------------------------------------------------------------------------
__global__ void wconv_kernel(const float* __restrict__ W) {
    int i = blockIdx.x * 256 + threadIdx.x;
    float4 v = *(const float4*)(W + (size_t)i * 4);
    uint2 p;
    p.x = pack_f16(v.x, v.y);
    p.y = pack_f16(v.z, v.w);
    *(uint2*)&g_wh[(size_t)i * 4] = p;
}

// ---------------------------------------------------------------------------
// QKV GEMM, pure fp16 mma.sync, TRIPLE-buffered cp.async, ONE barrier/slab.
// CTA tile 128x128, 8 warps (2m x 4n), warp tile 64x32, k-slab 32.
// Epilogue folds softmax scale (0.125*log2e) into the Q columns (n < 512).
// ---------------------------------------------------------------------------
#define GEMM_SMEM 56832  // 3 bufs x (As 10240 + Bs 8704)

__global__ void __launch_bounds__(256, 2) qkv_gemm_kernel(const float* __restrict__ bias) {
    extern __shared__ char gsm[];
    uint32_t gs = (uint32_t)__cvta_generic_to_shared(gsm);

    int t = threadIdx.x, lane = t & 31, wid = t >> 5;
    int g = lane >> 2, c = lane & 3;
    int grp = lane >> 3, r8 = lane & 7;
    int wm = (wid >> 2) * 64, wn = (wid & 3) * 32;
    int m0 = blockIdx.y * 128, n0 = blockIdx.x * 128;

    int arow_off = ((grp & 1) * 8 + r8) * 80 + (grp >> 1) * 16;
    const char* Ab = (const char*)g_xnh + (size_t)m0 * (CDIM * 2);
    const char* Bb = (const char*)g_wh + (size_t)n0 * 2;

    {
        #pragma unroll
        for (int j = 0; j < 2; j++) {
            int id = t + j * 256;
            int row = id >> 2, cc = id & 3;
            cp16(gs + row * 80 + cc * 16,
                 Ab + (size_t)row * (CDIM * 2) + cc * 16);
            int brow = id >> 4, bcc = id & 15;
            cp16(gs + 10240 + brow * 272 + bcc * 16,
                 Bb + (size_t)brow * (C3 * 2) + bcc * 16);
        }
        CP_COMMIT();
    }

    float acc[4][4][4] = {};
    int rbuf = 0;

    for (int s = 0; s < CDIM / 32; s++) {
        if (s + 1 < CDIM / 32) {
            int nbuf = (rbuf + 1 == 3) ? 0 : rbuf + 1;
            uint32_t bb = gs + nbuf * 18944;
            #pragma unroll
            for (int j = 0; j < 2; j++) {
                int id = t + j * 256;
                int row = id >> 2, cc = id & 3;
                cp16(bb + row * 80 + cc * 16,
                     Ab + (size_t)row * (CDIM * 2) + (s + 1) * 64 + cc * 16);
                int brow = id >> 4, bcc = id & 15;
                cp16(bb + 10240 + brow * 272 + bcc * 16,
                     Bb + (size_t)((s + 1) * 32 + brow) * (C3 * 2) + bcc * 16);
            }
        }
        CP_COMMIT();
        CP_WAIT1();
        __syncthreads();

        char* As = gsm + rbuf * 18944;
        char* Bs = As + 10240;

        #pragma unroll
        for (int kc = 0; kc < 2; kc++) {
            uint32_t af[4][4];
            #pragma unroll
            for (int mt = 0; mt < 4; mt++) {
                int ao = (wm + mt * 16) * 80 + kc * 32 + arow_off;
                ldmatrix_x4(af[mt][0], af[mt][1], af[mt][2], af[mt][3], As + ao);
            }
            #pragma unroll
            for (int ntp = 0; ntp < 2; ntp++) {
                int bo = (kc * 16 + (lane & 15)) * 272 + (wn + ntp * 16) * 2
                       + ((lane >> 4) << 4);
                uint32_t b0, b1, b2, b3;
                ldmatrix_x4_trans(b0, b1, b2, b3, Bs + bo);
                #pragma unroll
                for (int mt = 0; mt < 4; mt++) {
                    mma_f16(acc[mt][2*ntp],   af[mt], b0, b1);
                    mma_f16(acc[mt][2*ntp+1], af[mt], b2, b3);
                }
            }
        }
        rbuf = (rbuf + 1 == 3) ? 0 : rbuf + 1;
    }

    #pragma unroll
    for (int mt = 0; mt < 4; mt++) {
        int m = m0 + wm + mt * 16 + g;
        #pragma unroll
        for (int nt = 0; nt < 4; nt++) {
            int n = n0 + wn + nt * 8 + 2 * c;
            float sc = (n < CDIM) ? QK_LOG2_SCALE : 1.0f;
            float b0 = bias[n], b1 = bias[n + 1];
            #pragma unroll
            for (int rr = 0; rr < 2; rr++) {
                float s0 = (acc[mt][nt][2 * rr]     + b0) * sc;
                float s1 = (acc[mt][nt][2 * rr + 1] + b1) * sc;
                size_t off = (size_t)(m + 8 * rr) * C3 + n;
                *(uint32_t*)&g_qkvh[off] = pack_f16(s0, s1);
            }
        }
    }
}

// ---------------------------------------------------------------------------
// Flash attention, fp16 mma.sync, occupancy 2.
// KV processed in 128-row PAIRS: 4 x 64-row buffers, ONE wait_group(0) +
// ONE barrier per pair (prefetch issued AFTER the barrier -> WAR-safe).
// Softmax = ex2.approx.f16x2 directly on S fragments. Row sums: fp16
// add.f16x2 pre-sum of P across np, then one ones-B MMA per mt per pass.
// Warp m-tile 32, CTA Q-tile 256.
// ---------------------------------------------------------------------------
#define ATTN_SMEM 110592  // Q 256x144 = 36864 + 4 bufs x (K 9216 + V 9216)
#define ONES_H2 0x3C003C00u

__global__ void __launch_bounds__(256, 2) attn_kernel() {
    extern __shared__ char dsm[];
    char* Qs = dsm;                        // 256 x 144 B
    char* KV = dsm + 36864;                // 4 bufs x [K, V] x (64 x 144)
    uint32_t kvs = (uint32_t)__cvta_generic_to_shared(KV);

    int t = threadIdx.x, lane = t & 31, wid = t >> 5;
    int g = lane >> 2, c = lane & 3;
    int grp = lane >> 3, r8 = lane & 7;
    int bh = blockIdx.y, b = bh >> 3, h = bh & 7;
    int m0 = blockIdx.x * 256;
    int wrow = wid * 32;

    const char* qkb = (const char*)g_qkvh;
    size_t qoff  = (size_t)(b * NSEQ + m0) * 3072 + h * 128;
    size_t kbase = (size_t)(b * NSEQ) * 3072 + 1024 + h * 128;
    size_t vbase = kbase + 1024;

    int frag_off = ((grp & 1) * 8 + r8) * 144 + (grp >> 1) * 16;  // K & Q ldmatrix
    int vrow_off = (lane & 15) * 144 + ((lane >> 4) << 4);        // V trans

    // --- prologue: prefetch chunks 0 and 1 into buffers 0 and 1 ---
    {
        #pragma unroll
        for (int cth = 0; cth < 2; cth++) {
            uint32_t bb = kvs + cth * 18432;
            #pragma unroll
            for (int j = 0; j < 2; j++) {
                int id = t + j * 256;
                int row = id >> 3, c16 = id & 7;
                size_t go = (size_t)(cth * 64 + row) * 3072 + c16 * 16;
                uint32_t doff = row * 144 + c16 * 16;
                cp16(bb + doff,        qkb + kbase + go);
                cp16(bb + 9216 + doff, qkb + vbase + go);
            }
        }
        CP_COMMIT();
    }

    // --- stage Q (256 rows x 128 B), 8 threads/row, coalesced ---
    {
        #pragma unroll
        for (int j = 0; j < 8; j++) {
            int id = t + j * 256;
            int row = id >> 3, c16 = id & 7;
            size_t so = qoff + (size_t)row * 3072 + c16 * 16;
            *(uint4*)(Qs + row * 144 + c16 * 16) = *(const uint4*)(qkb + so);
        }
    }

    float oacc[2][8][4] = {};
    float rsacc[2][4] = {};

    for (int i = 0; i < NSEQ / 128; i++) {
        CP_WAIT0();        // pair i data complete (only outstanding group)
        __syncthreads();   // visible to all warps; all warps done with pair i-1

        // Prefetch pair i+1 (AFTER barrier -> safe to overwrite bufs last
        // read in pair i-1). Overlaps compute of pair i below.
        if (i + 1 < NSEQ / 128) {
            #pragma unroll
            for (int cth = 0; cth < 2; cth++) {
                int chunk = 2 * i + 2 + cth;
                uint32_t bb = kvs + (chunk & 3) * 18432;
                #pragma unroll
                for (int j = 0; j < 2; j++) {
                    int id = t + j * 256;
                    int row = id >> 3, c16 = id & 7;
                    size_t go = (size_t)(chunk * 64 + row) * 3072 + c16 * 16;
                    uint32_t doff = row * 144 + c16 * 16;
                    cp16(bb + doff,        qkb + kbase + go);
                    cp16(bb + 9216 + doff, qkb + vbase + go);
                }
            }
            CP_COMMIT();
        }

        // --- compute both 64-kv chunks of this pair ---
        #pragma unroll
        for (int p = 0; p < 2; p++) {
            int chunk = 2 * i + p;
            char* Kp = KV + (chunk & 3) * 18432;
            char* Vp = Kp + 9216;

            // S = Q K^T, single fp16 chain over k=64.
            uint32_t S[4][2][4] = {};
            #pragma unroll
            for (int kc = 0; kc < 4; kc++) {
                uint32_t q0[4], q1[4];
                ldmatrix_x4(q0[0], q0[1], q0[2], q0[3],
                            Qs + wrow * 144 + kc * 32 + frag_off);
                ldmatrix_x4(q1[0], q1[1], q1[2], q1[3],
                            Qs + (wrow + 16) * 144 + kc * 32 + frag_off);
                #pragma unroll
                for (int np = 0; np < 4; np++) {
                    uint32_t k0, k1, k2, k3;
                    ldmatrix_x4(k0, k1, k2, k3, Kp + np * 2304 + kc * 32 + frag_off);
                    mma_f16_h(&S[np][0][0], q0, k0, k2);
                    mma_f16_h(&S[np][0][2], q0, k1, k3);
                    mma_f16_h(&S[np][1][0], q1, k0, k2);
                    mma_f16_h(&S[np][1][2], q1, k1, k3);
                }
            }

            // Softmax + O per np; accumulate P in fp16 for row sums.
            uint32_t psum[2][4] = {};
            #pragma unroll
            for (int np = 0; np < 4; np++) {
                uint32_t pfr[2][4];
                #pragma unroll
                for (int mt = 0; mt < 2; mt++) {
                    H2EXP2(pfr[mt][0], S[np][mt][0]);
                    H2EXP2(pfr[mt][1], S[np][mt][1]);
                    H2EXP2(pfr[mt][2], S[np][mt][2]);
                    H2EXP2(pfr[mt][3], S[np][mt][3]);
                    HADD2(psum[mt][0], pfr[mt][0]);
                    HADD2(psum[mt][1], pfr[mt][1]);
                    HADD2(psum[mt][2], pfr[mt][2]);
                    HADD2(psum[mt][3], pfr[mt][3]);
                }
                #pragma unroll
                for (int dt = 0; dt < 4; dt++) {
                    int vo = np * 16 * 144 + dt * 32 + vrow_off;
                    uint32_t h0, h1, h2, h3;
                    ldmatrix_x4_trans(h0, h1, h2, h3, Vp + vo);
                    #pragma unroll
                    for (int mt = 0; mt < 2; mt++) {
                        mma_f16(oacc[mt][2*dt],     pfr[mt], h0, h1);
                        mma_f16(oacc[mt][2*dt + 1], pfr[mt], h2, h3);
                    }
                }
            }
            // row sums: one ones-B MMA per mt per 64-pass (MMA linear in A)
            #pragma unroll
            for (int mt = 0; mt < 2; mt++)
                mma_f16(rsacc[mt], psum[mt], ONES_H2, ONES_H2);
        }
    }

    // Normalize and store (rsacc[mt][0]=row g, rsacc[mt][2]=row g+8)
    #pragma unroll
    for (int mt = 0; mt < 2; mt++) {
        float inv0 = 1.f / rsacc[mt][0];
        float inv1 = 1.f / rsacc[mt][2];

        float* o0 = g_val + (size_t)(b * NSEQ + m0 + wrow + mt * 16 + g) * CDIM
                  + h * HD + 2 * c;
        float* o1 = o0 + (size_t)8 * CDIM;
        #pragma unroll
        for (int n = 0; n < 8; n++) {
            float2 v0 = { oacc[mt][n][0] * inv0, oacc[mt][n][1] * inv0 };
            float2 v1 = { oacc[mt][n][2] * inv1, oacc[mt][n][3] * inv1 };
            *(float2*)(o0 + n * 8) = v0;
            *(float2*)(o1 + n * 8) = v1;
        }
    }
}

// ---------------------------------------------------------------------------
// Post-LayerNorm + residual, 2 rows per warp (interleaved, MLP=8):
// out = xn + LN(val)*g + beta.  Grid: NROWS/16 blocks x 256 threads.
// ---------------------------------------------------------------------------
__global__ void post_ln_kernel(const float* __restrict__ g,
                               const float* __restrict__ beta,
                               float* __restrict__ out) {
    int wid = threadIdx.x >> 5, lane = threadIdx.x & 31;
    int rowa = blockIdx.x * 16 + wid * 2;
    int rowb = rowa + 1;
    const float* va_p = g_val + (size_t)rowa * CDIM;
    const float* vb_p = g_val + (size_t)rowb * CDIM;
    float4 va[4], vb[4];
    #pragma unroll
    for (int i = 0; i < 4; i++) {
        va[i] = *(const float4*)(va_p + (lane + i * 32) * 4);
        vb[i] = *(const float4*)(vb_p + (lane + i * 32) * 4);
    }
    float sa = 0.f, sa2 = 0.f, sb = 0.f, sb2 = 0.f;
    #pragma unroll
    for (int i = 0; i < 4; i++) {
        sa  += (va[i].x + va[i].y) + (va[i].z + va[i].w);
        sa2 += (va[i].x * va[i].x + va[i].y * va[i].y) + (va[i].z * va[i].z + va[i].w * va[i].w);
        sb  += (vb[i].x + vb[i].y) + (vb[i].z + vb[i].w);
        sb2 += (vb[i].x * vb[i].x + vb[i].y * vb[i].y) + (vb[i].z * vb[i].z + vb[i].w * vb[i].w);
    }
    #pragma unroll
    for (int o = 16; o > 0; o >>= 1) {
        sa  += __shfl_xor_sync(0xffffffffu, sa,  o);
        sa2 += __shfl_xor_sync(0xffffffffu, sa2, o);
        sb  += __shfl_xor_sync(0xffffffffu, sb,  o);
        sb2 += __shfl_xor_sync(0xffffffffu, sb2, o);
    }
    float ma = sa * (1.f / CDIM), mb = sb * (1.f / CDIM);
    float ra = rsqrtf(sa2 * (1.f / CDIM) - ma * ma + 1e-5f);
    float rb = rsqrtf(sb2 * (1.f / CDIM) - mb * mb + 1e-5f);
    const float* xa = g_xn + (size_t)rowa * CDIM;
    const float* xb = g_xn + (size_t)rowb * CDIM;
    float* oa = out + (size_t)rowa * CDIM;
    float* ob = out + (size_t)rowb * CDIM;
    #pragma unroll
    for (int i = 0; i < 4; i++) {
        int idx = (lane + i * 32) * 4;
        float4 gv = *(const float4*)(g + idx);
        float4 bv = *(const float4*)(beta + idx);
        float4 x1 = *(const float4*)(xa + idx);
        float4 x2 = *(const float4*)(xb + idx);
        float4 o1, o2;
        o1.x = x1.x + (va[i].x - ma) * ra * gv.x + bv.x;
        o1.y = x1.y + (va[i].y - ma) * ra * gv.y + bv.y;
        o1.z = x1.z + (va[i].z - ma) * ra * gv.z + bv.z;
        o1.w = x1.w + (va[i].w - ma) * ra * gv.w + bv.w;
        o2.x = x2.x + (vb[i].x - mb) * rb * gv.x + bv.x;
        o2.y = x2.y + (vb[i].y - mb) * rb * gv.y + bv.y;
        o2.z = x2.z + (vb[i].z - mb) * rb * gv.z + bv.z;
        o2.w = x2.w + (vb[i].w - mb) * rb * gv.w + bv.w;
        *(float4*)(oa + idx) = o1;
        *(float4*)(ob + idx) = o2;
    }
}

// ---------------------------------------------------------------------------
extern "C" void kernel_launch(void* const* d_in, const int* in_sizes, int n_in,
                              void* d_out, int out_size) {
    const float* x     = (const float*)d_in[0];
    const float* w_qkv = (const float*)d_in[1];
    const float* b_qkv = (const float*)d_in[2];
    const float* g_pre = (const float*)d_in[3];
    const float* beta_pre  = (const float*)d_in[4];
    const float* g_post    = (const float*)d_in[5];
    const float* beta_post = (const float*)d_in[6];
    float* out = (float*)d_out;

    (void)in_sizes; (void)n_in; (void)out_size;

    cudaFuncSetAttribute(attn_kernel,
                         cudaFuncAttributeMaxDynamicSharedMemorySize, ATTN_SMEM);
    cudaFuncSetAttribute(attn_kernel,
                         cudaFuncAttributePreferredSharedMemoryCarveout, 100);
    cudaFuncSetAttribute(qkv_gemm_kernel,
                         cudaFuncAttributeMaxDynamicSharedMemorySize, GEMM_SMEM);

    wconv_kernel<<<(CDIM * C3) / 1024, 256>>>(w_qkv);
    pre_ln_kernel<<<NROWS / 16, 256>>>(x, g_pre, beta_pre);

    dim3 ggrid(C3 / 128, NROWS / 128);
    qkv_gemm_kernel<<<ggrid, 256, GEMM_SMEM>>>(b_qkv);

    dim3 agrid(NSEQ / 256, BATCH * NH);
    attn_kernel<<<agrid, 256, ATTN_SMEM>>>();

    post_ln_kernel<<<NROWS / 16, 256>>>(g_post, beta_post, out);
}

// round 16
// speedup vs baseline: 1.1777x; 1.1777x over previous
#include <cuda_runtime.h>
#include <cuda_fp16.h>
#include <cstdint>
#include <cstddef>

// Problem constants
#define BATCH 2
#define NSEQ 4096
#define CDIM 512
#define C3   1536
#define NH   8
#define HD   64
#define NROWS (BATCH*NSEQ)      // 8192
#define QK_LOG2_SCALE (0.125f * 1.44269504f)

// Scratch (allocation-free rule: device globals)
__device__ float  g_xn  [(size_t)NROWS * CDIM];  // fp32 pre-norm (residual)
__device__ __half g_xnh [(size_t)NROWS * CDIM];  // fp16 pre-norm (GEMM A)
__device__ __half g_wh  [(size_t)CDIM * C3];     // fp16 W
__device__ __half g_qkvh[(size_t)NROWS * C3];    // fp16 qkv (Q pre-scaled)
__device__ float  g_val [(size_t)NROWS * CDIM];  // attention output

static __device__ __forceinline__ uint32_t pack_f16(float lo, float hi) {
    __half2 p = __floats2half2_rn(lo, hi);
    return *(uint32_t*)&p;
}
// fp32-accumulator fp16 mma
static __device__ __forceinline__ void mma_f16(float* c, const uint32_t* a,
                                               uint32_t b0, uint32_t b1) {
    asm volatile(
        "mma.sync.aligned.m16n8k16.row.col.f32.f16.f16.f32 "
        "{%0,%1,%2,%3},{%4,%5,%6,%7},{%8,%9},{%0,%1,%2,%3};"
        : "+f"(c[0]), "+f"(c[1]), "+f"(c[2]), "+f"(c[3])
        : "r"(a[0]), "r"(a[1]), "r"(a[2]), "r"(a[3]), "r"(b0), "r"(b1));
}
// fp16-accumulator fp16 mma (2 packed f16x2 accumulator regs)
static __device__ __forceinline__ void mma_f16_h(uint32_t* c, const uint32_t* a,
                                                 uint32_t b0, uint32_t b1) {
    asm volatile(
        "mma.sync.aligned.m16n8k16.row.col.f16.f16.f16.f16 "
        "{%0,%1},{%2,%3,%4,%5},{%6,%7},{%0,%1};"
        : "+r"(c[0]), "+r"(c[1])
        : "r"(a[0]), "r"(a[1]), "r"(a[2]), "r"(a[3]), "r"(b0), "r"(b1));
}
// packed fp16x2 exp2 (MUFU, one instr for two exps; output stays fp16)
#define H2EXP2(d, s) asm("ex2.approx.f16x2 %0, %1;" : "=r"(d) : "r"(s))
// packed fp16x2 add (accumulate P fragments for row sums)
#define HADD2(acc, v) asm("add.rn.f16x2 %0, %0, %1;" : "+r"(acc) : "r"(v))

static __device__ __forceinline__ void ldmatrix_x4(uint32_t& r0, uint32_t& r1,
                                                   uint32_t& r2, uint32_t& r3,
                                                   const void* p) {
    uint32_t addr = (uint32_t)__cvta_generic_to_shared(p);
    asm volatile("ldmatrix.sync.aligned.m8n8.x4.shared.b16 {%0,%1,%2,%3}, [%4];"
                 : "=r"(r0), "=r"(r1), "=r"(r2), "=r"(r3) : "r"(addr));
}
static __device__ __forceinline__ void ldmatrix_x4_trans(uint32_t& r0, uint32_t& r1,
                                                         uint32_t& r2, uint32_t& r3,
                                                         const void* p) {
    uint32_t addr = (uint32_t)__cvta_generic_to_shared(p);
    asm volatile("ldmatrix.sync.aligned.m8n8.x4.trans.shared.b16 {%0,%1,%2,%3}, [%4];"
                 : "=r"(r0), "=r"(r1), "=r"(r2), "=r"(r3) : "r"(addr));
}
static __device__ __forceinline__ void cp16(uint32_t dst, const void* src) {
    asm volatile("cp.async.cg.shared.global [%0], [%1], 16;" :: "r"(dst), "l"(src) : "memory");
}
#define CP_COMMIT() asm volatile("cp.async.commit_group;" ::: "memory")
#define CP_WAIT1()  asm volatile("cp.async.wait_group 1;" ::: "memory")

// ---------------------------------------------------------------------------
// Pre-LayerNorm (fp32), 2 rows per warp (interleaved loads for MLP=8);
// emits fp32 + fp16 copies.  Grid: NROWS/16 blocks x 256 threads.
// ---------------------------------------------------------------------------
__global__ void pre_ln_kernel(const float* __restrict__ x,
                              const float* __restrict__ g,
                              const float* __restrict__ beta) {
    int wid = threadIdx.x >> 5, lane = threadIdx.x & 31;
    int rowa = blockIdx.x * 16 + wid * 2;
    int rowb = rowa + 1;
    const float* xa = x + (size_t)rowa * CDIM;
    const float* xb = x + (size_t)rowb * CDIM;
    float4 va[4], vb[4];
    #pragma unroll
    for (int i = 0; i < 4; i++) {
        va[i] = *(const float4*)(xa + (lane + i * 32) * 4);
        vb[i] = *(const float4*)(xb + (lane + i * 32) * 4);
    }
    float sa = 0.f, sa2 = 0.f, sb = 0.f, sb2 = 0.f;
    #pragma unroll
    for (int i = 0; i < 4; i++) {
        sa  += (va[i].x + va[i].y) + (va[i].z + va[i].w);
        sa2 += (va[i].x * va[i].x + va[i].y * va[i].y) + (va[i].z * va[i].z + va[i].w * va[i].w);
        sb  += (vb[i].x + vb[i].y) + (vb[i].z + vb[i].w);
        sb2 += (vb[i].x * vb[i].x + vb[i].y * vb[i].y) + (vb[i].z * vb[i].z + vb[i].w * vb[i].w);
    }
    #pragma unroll
    for (int o = 16; o > 0; o >>= 1) {
        sa  += __shfl_xor_sync(0xffffffffu, sa,  o);
        sa2 += __shfl_xor_sync(0xffffffffu, sa2, o);
        sb  += __shfl_xor_sync(0xffffffffu, sb,  o);
        sb2 += __shfl_xor_sync(0xffffffffu, sb2, o);
    }
    float ma = sa * (1.f / CDIM), mb = sb * (1.f / CDIM);
    float ra = rsqrtf(sa2 * (1.f / CDIM) - ma * ma + 1e-5f);
    float rb = rsqrtf(sb2 * (1.f / CDIM) - mb * mb + 1e-5f);
    float*  oa = g_xn  + (size_t)rowa * CDIM;
    float*  ob = g_xn  + (size_t)rowb * CDIM;
    __half* ha = g_xnh + (size_t)rowa * CDIM;
    __half* hb = g_xnh + (size_t)rowb * CDIM;
    #pragma unroll
    for (int i = 0; i < 4; i++) {
        int idx = (lane + i * 32) * 4;
        float4 gv = *(const float4*)(g + idx);
        float4 bv = *(const float4*)(beta + idx);
        float4 o1, o2;
        o1.x = (va[i].x - ma) * ra * gv.x + bv.x;
        o1.y = (va[i].y - ma) * ra * gv.y + bv.y;
        o1.z = (va[i].z - ma) * ra * gv.z + bv.z;
        o1.w = (va[i].w - ma) * ra * gv.w + bv.w;
        o2.x = (vb[i].x - mb) * rb * gv.x + bv.x;
        o2.y = (vb[i].y - mb) * rb * gv.y + bv.y;
        o2.z = (vb[i].z - mb) * rb * gv.z + bv.z;
        o2.w = (vb[i].w - mb) * rb * gv.w + bv.w;
        *(float4*)(oa + idx) = o1;
        *(float4*)(ob + idx) = o2;
        uint2 p1, p2;
        p1.x = pack_f16(o1.x, o1.y); p1.y = pack_f16(o1.z, o1.w);
        p2.x = pack_f16(o2.x, o2.y); p2.y = pack_f16(o2.z, o2.w);
        *(uint2*)(ha + idx) = p1;
        *(uint2*)(hb + idx) = p2;
    }
}

// ---------------------------------------------------------------------------
// W fp32 -> fp16 conversion (once per launch).
// ---------------------------------------------------------------------------
__global__ void wconv_kernel(const float* __restrict__ W) {
    int i = blockIdx.x * 256 + threadIdx.x;
    float4 v = *(const float4*)(W + (size_t)i * 4);
    uint2 p;
    p.x = pack_f16(v.x, v.y);
    p.y = pack_f16(v.z, v.w);
    *(uint2*)&g_wh[(size_t)i * 4] = p;
}

// ---------------------------------------------------------------------------
// QKV GEMM, pure fp16 mma.sync, TRIPLE-buffered cp.async, ONE barrier/slab.
// CTA tile 128x128, 8 warps (2m x 4n), warp tile 64x32, k-slab 32.
// Epilogue folds softmax scale (0.125*log2e) into the Q columns (n < 512).
// ---------------------------------------------------------------------------
#define GEMM_SMEM 56832  // 3 bufs x (As 10240 + Bs 8704)

__global__ void __launch_bounds__(256, 2) qkv_gemm_kernel(const float* __restrict__ bias) {
    extern __shared__ char gsm[];
    uint32_t gs = (uint32_t)__cvta_generic_to_shared(gsm);

    int t = threadIdx.x, lane = t & 31, wid = t >> 5;
    int g = lane >> 2, c = lane & 3;
    int grp = lane >> 3, r8 = lane & 7;
    int wm = (wid >> 2) * 64, wn = (wid & 3) * 32;
    int m0 = blockIdx.y * 128, n0 = blockIdx.x * 128;

    int arow_off = ((grp & 1) * 8 + r8) * 80 + (grp >> 1) * 16;
    const char* Ab = (const char*)g_xnh + (size_t)m0 * (CDIM * 2);
    const char* Bb = (const char*)g_wh + (size_t)n0 * 2;

    {
        #pragma unroll
        for (int j = 0; j < 2; j++) {
            int id = t + j * 256;
            int row = id >> 2, cc = id & 3;
            cp16(gs + row * 80 + cc * 16,
                 Ab + (size_t)row * (CDIM * 2) + cc * 16);
            int brow = id >> 4, bcc = id & 15;
            cp16(gs + 10240 + brow * 272 + bcc * 16,
                 Bb + (size_t)brow * (C3 * 2) + bcc * 16);
        }
        CP_COMMIT();
    }

    float acc[4][4][4] = {};
    int rbuf = 0;

    for (int s = 0; s < CDIM / 32; s++) {
        if (s + 1 < CDIM / 32) {
            int nbuf = (rbuf + 1 == 3) ? 0 : rbuf + 1;
            uint32_t bb = gs + nbuf * 18944;
            #pragma unroll
            for (int j = 0; j < 2; j++) {
                int id = t + j * 256;
                int row = id >> 2, cc = id & 3;
                cp16(bb + row * 80 + cc * 16,
                     Ab + (size_t)row * (CDIM * 2) + (s + 1) * 64 + cc * 16);
                int brow = id >> 4, bcc = id & 15;
                cp16(bb + 10240 + brow * 272 + bcc * 16,
                     Bb + (size_t)((s + 1) * 32 + brow) * (C3 * 2) + bcc * 16);
            }
        }
        CP_COMMIT();
        CP_WAIT1();
        __syncthreads();

        char* As = gsm + rbuf * 18944;
        char* Bs = As + 10240;

        #pragma unroll
        for (int kc = 0; kc < 2; kc++) {
            uint32_t af[4][4];
            #pragma unroll
            for (int mt = 0; mt < 4; mt++) {
                int ao = (wm + mt * 16) * 80 + kc * 32 + arow_off;
                ldmatrix_x4(af[mt][0], af[mt][1], af[mt][2], af[mt][3], As + ao);
            }
            #pragma unroll
            for (int ntp = 0; ntp < 2; ntp++) {
                int bo = (kc * 16 + (lane & 15)) * 272 + (wn + ntp * 16) * 2
                       + ((lane >> 4) << 4);
                uint32_t b0, b1, b2, b3;
                ldmatrix_x4_trans(b0, b1, b2, b3, Bs + bo);
                #pragma unroll
                for (int mt = 0; mt < 4; mt++) {
                    mma_f16(acc[mt][2*ntp],   af[mt], b0, b1);
                    mma_f16(acc[mt][2*ntp+1], af[mt], b2, b3);
                }
            }
        }
        rbuf = (rbuf + 1 == 3) ? 0 : rbuf + 1;
    }

    #pragma unroll
    for (int mt = 0; mt < 4; mt++) {
        int m = m0 + wm + mt * 16 + g;
        #pragma unroll
        for (int nt = 0; nt < 4; nt++) {
            int n = n0 + wn + nt * 8 + 2 * c;
            float sc = (n < CDIM) ? QK_LOG2_SCALE : 1.0f;
            float b0 = bias[n], b1 = bias[n + 1];
            #pragma unroll
            for (int rr = 0; rr < 2; rr++) {
                float s0 = (acc[mt][nt][2 * rr]     + b0) * sc;
                float s1 = (acc[mt][nt][2 * rr + 1] + b1) * sc;
                size_t off = (size_t)(m + 8 * rr) * C3 + n;
                *(uint32_t*)&g_qkvh[off] = pack_f16(s0, s1);
            }
        }
    }
}

// ---------------------------------------------------------------------------
// Flash attention (R13/R14 buffering restored): fp16 mma.sync, occupancy 2,
// ex2.approx.f16x2 directly on S fragments, triple-buffered cp.async K/V
// with wait_group(1) + one barrier per 64-kv iteration.
// Row sums: fp16 add.f16x2 pre-sum of P across np, ONE ones-B MMA per mt
// per iteration (2 MMAs instead of 8).
// ---------------------------------------------------------------------------
#define ATTN_SMEM 92160  // Q 256x144 = 36864 + 3 bufs x (K 9216 + V 9216)
#define ONES_H2 0x3C003C00u

__global__ void __launch_bounds__(256, 2) attn_kernel() {
    extern __shared__ char dsm[];
    char* Qs = dsm;                        // 256 x 144 B
    char* KV = dsm + 36864;                // 3 bufs x [K, V] x (64 x 144)
    uint32_t kvs = (uint32_t)__cvta_generic_to_shared(KV);

    int t = threadIdx.x, lane = t & 31, wid = t >> 5;
    int g = lane >> 2, c = lane & 3;
    int grp = lane >> 3, r8 = lane & 7;
    int bh = blockIdx.y, b = bh >> 3, h = bh & 7;
    int m0 = blockIdx.x * 256;
    int wrow = wid * 32;

    const char* qkb = (const char*)g_qkvh;
    size_t qoff  = (size_t)(b * NSEQ + m0) * 3072 + h * 128;
    size_t kbase = (size_t)(b * NSEQ) * 3072 + 1024 + h * 128;
    size_t vbase = kbase + 1024;

    int frag_off = ((grp & 1) * 8 + r8) * 144 + (grp >> 1) * 16;  // K & Q ldmatrix
    int vrow_off = (lane & 15) * 144 + ((lane >> 4) << 4);        // V trans

    // --- prefetch KV chunk 0 into buffer 0 ---
    {
        #pragma unroll
        for (int j = 0; j < 2; j++) {
            int id = t + j * 256;
            int row = id >> 3, c16 = id & 7;
            size_t go = (size_t)row * 3072 + c16 * 16;
            uint32_t doff = row * 144 + c16 * 16;
            cp16(kvs + doff,        qkb + kbase + go);
            cp16(kvs + 9216 + doff, qkb + vbase + go);
        }
        CP_COMMIT();
    }

    // --- stage Q (256 rows x 128 B), 8 threads/row, coalesced ---
    {
        #pragma unroll
        for (int j = 0; j < 8; j++) {
            int id = t + j * 256;
            int row = id >> 3, c16 = id & 7;
            size_t so = qoff + (size_t)row * 3072 + c16 * 16;
            *(uint4*)(Qs + row * 144 + c16 * 16) = *(const uint4*)(qkb + so);
        }
    }

    float oacc[2][8][4] = {};
    float rsacc[2][4] = {};
    int rbuf = 0;

    for (int it = 0; it < NSEQ / 64; it++) {
        // Prefetch next chunk into buffer (it+1)%3.
        // WAR safety: that buffer was last read in iter it-2, which
        // completed before the (single) barrier of iter it-1.
        if (it + 1 < NSEQ / 64) {
            int nbuf = (rbuf + 1 == 3) ? 0 : rbuf + 1;
            uint32_t bb = kvs + nbuf * 18432;
            #pragma unroll
            for (int j = 0; j < 2; j++) {
                int id = t + j * 256;
                int row = id >> 3, c16 = id & 7;
                size_t go = (size_t)((it + 1) * 64 + row) * 3072 + c16 * 16;
                uint32_t doff = row * 144 + c16 * 16;
                cp16(bb + doff,        qkb + kbase + go);
                cp16(bb + 9216 + doff, qkb + vbase + go);
            }
        }
        CP_COMMIT();
        CP_WAIT1();
        __syncthreads();   // single barrier per iteration

        char* Kp = KV + rbuf * 18432;
        char* Vp = Kp + 9216;

        // S = Q K^T, single fp16 chain over k=64.
        uint32_t S[4][2][4] = {};
        #pragma unroll
        for (int kc = 0; kc < 4; kc++) {
            uint32_t q0[4], q1[4];
            ldmatrix_x4(q0[0], q0[1], q0[2], q0[3],
                        Qs + wrow * 144 + kc * 32 + frag_off);
            ldmatrix_x4(q1[0], q1[1], q1[2], q1[3],
                        Qs + (wrow + 16) * 144 + kc * 32 + frag_off);
            #pragma unroll
            for (int np = 0; np < 4; np++) {
                uint32_t k0, k1, k2, k3;
                ldmatrix_x4(k0, k1, k2, k3, Kp + np * 2304 + kc * 32 + frag_off);
                mma_f16_h(&S[np][0][0], q0, k0, k2);
                mma_f16_h(&S[np][0][2], q0, k1, k3);
                mma_f16_h(&S[np][1][0], q1, k0, k2);
                mma_f16_h(&S[np][1][2], q1, k1, k3);
            }
        }

        // Softmax + O per np; accumulate P in fp16 for row sums.
        uint32_t psum[2][4] = {};
        #pragma unroll
        for (int np = 0; np < 4; np++) {
            uint32_t pfr[2][4];
            #pragma unroll
            for (int mt = 0; mt < 2; mt++) {
                H2EXP2(pfr[mt][0], S[np][mt][0]);
                H2EXP2(pfr[mt][1], S[np][mt][1]);
                H2EXP2(pfr[mt][2], S[np][mt][2]);
                H2EXP2(pfr[mt][3], S[np][mt][3]);
                HADD2(psum[mt][0], pfr[mt][0]);
                HADD2(psum[mt][1], pfr[mt][1]);
                HADD2(psum[mt][2], pfr[mt][2]);
                HADD2(psum[mt][3], pfr[mt][3]);
            }
            #pragma unroll
            for (int dt = 0; dt < 4; dt++) {
                int vo = np * 16 * 144 + dt * 32 + vrow_off;
                uint32_t h0, h1, h2, h3;
                ldmatrix_x4_trans(h0, h1, h2, h3, Vp + vo);
                #pragma unroll
                for (int mt = 0; mt < 2; mt++) {
                    mma_f16(oacc[mt][2*dt],     pfr[mt], h0, h1);
                    mma_f16(oacc[mt][2*dt + 1], pfr[mt], h2, h3);
                }
            }
        }
        // row sums: one ones-B MMA per mt per iteration (MMA linear in A)
        #pragma unroll
        for (int mt = 0; mt < 2; mt++)
            mma_f16(rsacc[mt], psum[mt], ONES_H2, ONES_H2);

        rbuf = (rbuf + 1 == 3) ? 0 : rbuf + 1;
    }

    // Normalize and store (rsacc[mt][0]=row g, rsacc[mt][2]=row g+8)
    #pragma unroll
    for (int mt = 0; mt < 2; mt++) {
        float inv0 = 1.f / rsacc[mt][0];
        float inv1 = 1.f / rsacc[mt][2];

        float* o0 = g_val + (size_t)(b * NSEQ + m0 + wrow + mt * 16 + g) * CDIM
                  + h * HD + 2 * c;
        float* o1 = o0 + (size_t)8 * CDIM;
        #pragma unroll
        for (int n = 0; n < 8; n++) {
            float2 v0 = { oacc[mt][n][0] * inv0, oacc[mt][n][1] * inv0 };
            float2 v1 = { oacc[mt][n][2] * inv1, oacc[mt][n][3] * inv1 };
            *(float2*)(o0 + n * 8) = v0;
            *(float2*)(o1 + n * 8) = v1;
        }
    }
}

// ---------------------------------------------------------------------------
// Post-LayerNorm + residual, 2 rows per warp (interleaved, MLP=8):
// out = xn + LN(val)*g + beta.  Grid: NROWS/16 blocks x 256 threads.
// ---------------------------------------------------------------------------
__global__ void post_ln_kernel(const float* __restrict__ g,
                               const float* __restrict__ beta,
                               float* __restrict__ out) {
    int wid = threadIdx.x >> 5, lane = threadIdx.x & 31;
    int rowa = blockIdx.x * 16 + wid * 2;
    int rowb = rowa + 1;
    const float* va_p = g_val + (size_t)rowa * CDIM;
    const float* vb_p = g_val + (size_t)rowb * CDIM;
    float4 va[4], vb[4];
    #pragma unroll
    for (int i = 0; i < 4; i++) {
        va[i] = *(const float4*)(va_p + (lane + i * 32) * 4);
        vb[i] = *(const float4*)(vb_p + (lane + i * 32) * 4);
    }
    float sa = 0.f, sa2 = 0.f, sb = 0.f, sb2 = 0.f;
    #pragma unroll
    for (int i = 0; i < 4; i++) {
        sa  += (va[i].x + va[i].y) + (va[i].z + va[i].w);
        sa2 += (va[i].x * va[i].x + va[i].y * va[i].y) + (va[i].z * va[i].z + va[i].w * va[i].w);
        sb  += (vb[i].x + vb[i].y) + (vb[i].z + vb[i].w);
        sb2 += (vb[i].x * vb[i].x + vb[i].y * vb[i].y) + (vb[i].z * vb[i].z + vb[i].w * vb[i].w);
    }
    #pragma unroll
    for (int o = 16; o > 0; o >>= 1) {
        sa  += __shfl_xor_sync(0xffffffffu, sa,  o);
        sa2 += __shfl_xor_sync(0xffffffffu, sa2, o);
        sb  += __shfl_xor_sync(0xffffffffu, sb,  o);
        sb2 += __shfl_xor_sync(0xffffffffu, sb2, o);
    }
    float ma = sa * (1.f / CDIM), mb = sb * (1.f / CDIM);
    float ra = rsqrtf(sa2 * (1.f / CDIM) - ma * ma + 1e-5f);
    float rb = rsqrtf(sb2 * (1.f / CDIM) - mb * mb + 1e-5f);
    const float* xa = g_xn + (size_t)rowa * CDIM;
    const float* xb = g_xn + (size_t)rowb * CDIM;
    float* oa = out + (size_t)rowa * CDIM;
    float* ob = out + (size_t)rowb * CDIM;
    #pragma unroll
    for (int i = 0; i < 4; i++) {
        int idx = (lane + i * 32) * 4;
        float4 gv = *(const float4*)(g + idx);
        float4 bv = *(const float4*)(beta + idx);
        float4 x1 = *(const float4*)(xa + idx);
        float4 x2 = *(const float4*)(xb + idx);
        float4 o1, o2;
        o1.x = x1.x + (va[i].x - ma) * ra * gv.x + bv.x;
        o1.y = x1.y + (va[i].y - ma) * ra * gv.y + bv.y;
        o1.z = x1.z + (va[i].z - ma) * ra * gv.z + bv.z;
        o1.w = x1.w + (va[i].w - ma) * ra * gv.w + bv.w;
        o2.x = x2.x + (vb[i].x - mb) * rb * gv.x + bv.x;
        o2.y = x2.y + (vb[i].y - mb) * rb * gv.y + bv.y;
        o2.z = x2.z + (vb[i].z - mb) * rb * gv.z + bv.z;
        o2.w = x2.w + (vb[i].w - mb) * rb * gv.w + bv.w;
        *(float4*)(oa + idx) = o1;
        *(float4*)(ob + idx) = o2;
    }
}

// ---------------------------------------------------------------------------
extern "C" void kernel_launch(void* const* d_in, const int* in_sizes, int n_in,
                              void* d_out, int out_size) {
    const float* x     = (const float*)d_in[0];
    const float* w_qkv = (const float*)d_in[1];
    const float* b_qkv = (const float*)d_in[2];
    const float* g_pre = (const float*)d_in[3];
    const float* beta_pre  = (const float*)d_in[4];
    const float* g_post    = (const float*)d_in[5];
    const float* beta_post = (const float*)d_in[6];
    float* out = (float*)d_out;

    (void)in_sizes; (void)n_in; (void)out_size;

    cudaFuncSetAttribute(attn_kernel,
                         cudaFuncAttributeMaxDynamicSharedMemorySize, ATTN_SMEM);
    cudaFuncSetAttribute(attn_kernel,
                         cudaFuncAttributePreferredSharedMemoryCarveout, 100);
    cudaFuncSetAttribute(qkv_gemm_kernel,
                         cudaFuncAttributeMaxDynamicSharedMemorySize, GEMM_SMEM);

    wconv_kernel<<<(CDIM * C3) / 1024, 256>>>(w_qkv);
    pre_ln_kernel<<<NROWS / 16, 256>>>(x, g_pre, beta_pre);

    dim3 ggrid(C3 / 128, NROWS / 128);
    qkv_gemm_kernel<<<ggrid, 256, GEMM_SMEM>>>(b_qkv);

    dim3 agrid(NSEQ / 256, BATCH * NH);
    attn_kernel<<<agrid, 256, ATTN_SMEM>>>();

    post_ln_kernel<<<NROWS / 16, 256>>>(g_post, beta_post, out);
}

// round 17
// speedup vs baseline: 1.2294x; 1.0438x over previous
#include <cuda_runtime.h>
#include <cuda_fp16.h>
#include <cstdint>
#include <cstddef>

// Problem constants
#define BATCH 2
#define NSEQ 4096
#define CDIM 512
#define C3   1536
#define NH   8
#define HD   64
#define NROWS (BATCH*NSEQ)      // 8192
#define QK_LOG2_SCALE (0.125f * 1.44269504f)

// Scratch (allocation-free rule: device globals)
__device__ __half g_xnh [(size_t)NROWS * CDIM];  // fp16 pre-norm (GEMM A + residual)
__device__ __half g_wh  [(size_t)CDIM * C3];     // fp16 W
__device__ __half g_qkvh[(size_t)NROWS * C3];    // fp16 qkv (Q pre-scaled)
__device__ __half g_valh[(size_t)NROWS * CDIM];  // fp16 attention output

static __device__ __forceinline__ uint32_t pack_f16(float lo, float hi) {
    __half2 p = __floats2half2_rn(lo, hi);
    return *(uint32_t*)&p;
}
// fp32-accumulator fp16 mma
static __device__ __forceinline__ void mma_f16(float* c, const uint32_t* a,
                                               uint32_t b0, uint32_t b1) {
    asm volatile(
        "mma.sync.aligned.m16n8k16.row.col.f32.f16.f16.f32 "
        "{%0,%1,%2,%3},{%4,%5,%6,%7},{%8,%9},{%0,%1,%2,%3};"
        : "+f"(c[0]), "+f"(c[1]), "+f"(c[2]), "+f"(c[3])
        : "r"(a[0]), "r"(a[1]), "r"(a[2]), "r"(a[3]), "r"(b0), "r"(b1));
}
// fp16-accumulator fp16 mma (2 packed f16x2 accumulator regs)
static __device__ __forceinline__ void mma_f16_h(uint32_t* c, const uint32_t* a,
                                                 uint32_t b0, uint32_t b1) {
    asm volatile(
        "mma.sync.aligned.m16n8k16.row.col.f16.f16.f16.f16 "
        "{%0,%1},{%2,%3,%4,%5},{%6,%7},{%0,%1};"
        : "+r"(c[0]), "+r"(c[1])
        : "r"(a[0]), "r"(a[1]), "r"(a[2]), "r"(a[3]), "r"(b0), "r"(b1));
}
// packed fp16x2 exp2 (MUFU, one instr for two exps; output stays fp16)
#define H2EXP2(d, s) asm("ex2.approx.f16x2 %0, %1;" : "=r"(d) : "r"(s))
// packed fp16x2 add (accumulate P fragments for row sums)
#define HADD2(acc, v) asm("add.rn.f16x2 %0, %0, %1;" : "+r"(acc) : "r"(v))

static __device__ __forceinline__ void ldmatrix_x4(uint32_t& r0, uint32_t& r1,
                                                   uint32_t& r2, uint32_t& r3,
                                                   const void* p) {
    uint32_t addr = (uint32_t)__cvta_generic_to_shared(p);
    asm volatile("ldmatrix.sync.aligned.m8n8.x4.shared.b16 {%0,%1,%2,%3}, [%4];"
                 : "=r"(r0), "=r"(r1), "=r"(r2), "=r"(r3) : "r"(addr));
}
static __device__ __forceinline__ void ldmatrix_x4_trans(uint32_t& r0, uint32_t& r1,
                                                         uint32_t& r2, uint32_t& r3,
                                                         const void* p) {
    uint32_t addr = (uint32_t)__cvta_generic_to_shared(p);
    asm volatile("ldmatrix.sync.aligned.m8n8.x4.trans.shared.b16 {%0,%1,%2,%3}, [%4];"
                 : "=r"(r0), "=r"(r1), "=r"(r2), "=r"(r3) : "r"(addr));
}
static __device__ __forceinline__ void cp16(uint32_t dst, const void* src) {
    asm volatile("cp.async.cg.shared.global [%0], [%1], 16;" :: "r"(dst), "l"(src) : "memory");
}
#define CP_COMMIT() asm volatile("cp.async.commit_group;" ::: "memory")
#define CP_WAIT1()  asm volatile("cp.async.wait_group 1;" ::: "memory")

// ---------------------------------------------------------------------------
// Pre-LayerNorm (fp32 math), 2 rows per warp; emits fp16 only.
// Grid: NROWS/16 blocks x 256 threads.
// ---------------------------------------------------------------------------
__global__ void pre_ln_kernel(const float* __restrict__ x,
                              const float* __restrict__ g,
                              const float* __restrict__ beta) {
    int wid = threadIdx.x >> 5, lane = threadIdx.x & 31;
    int rowa = blockIdx.x * 16 + wid * 2;
    int rowb = rowa + 1;
    const float* xa = x + (size_t)rowa * CDIM;
    const float* xb = x + (size_t)rowb * CDIM;
    float4 va[4], vb[4];
    #pragma unroll
    for (int i = 0; i < 4; i++) {
        va[i] = *(const float4*)(xa + (lane + i * 32) * 4);
        vb[i] = *(const float4*)(xb + (lane + i * 32) * 4);
    }
    float sa = 0.f, sa2 = 0.f, sb = 0.f, sb2 = 0.f;
    #pragma unroll
    for (int i = 0; i < 4; i++) {
        sa  += (va[i].x + va[i].y) + (va[i].z + va[i].w);
        sa2 += (va[i].x * va[i].x + va[i].y * va[i].y) + (va[i].z * va[i].z + va[i].w * va[i].w);
        sb  += (vb[i].x + vb[i].y) + (vb[i].z + vb[i].w);
        sb2 += (vb[i].x * vb[i].x + vb[i].y * vb[i].y) + (vb[i].z * vb[i].z + vb[i].w * vb[i].w);
    }
    #pragma unroll
    for (int o = 16; o > 0; o >>= 1) {
        sa  += __shfl_xor_sync(0xffffffffu, sa,  o);
        sa2 += __shfl_xor_sync(0xffffffffu, sa2, o);
        sb  += __shfl_xor_sync(0xffffffffu, sb,  o);
        sb2 += __shfl_xor_sync(0xffffffffu, sb2, o);
    }
    float ma = sa * (1.f / CDIM), mb = sb * (1.f / CDIM);
    float ra = rsqrtf(sa2 * (1.f / CDIM) - ma * ma + 1e-5f);
    float rb = rsqrtf(sb2 * (1.f / CDIM) - mb * mb + 1e-5f);
    __half* ha = g_xnh + (size_t)rowa * CDIM;
    __half* hb = g_xnh + (size_t)rowb * CDIM;
    #pragma unroll
    for (int i = 0; i < 4; i++) {
        int idx = (lane + i * 32) * 4;
        float4 gv = *(const float4*)(g + idx);
        float4 bv = *(const float4*)(beta + idx);
        uint2 p1, p2;
        p1.x = pack_f16((va[i].x - ma) * ra * gv.x + bv.x,
                        (va[i].y - ma) * ra * gv.y + bv.y);
        p1.y = pack_f16((va[i].z - ma) * ra * gv.z + bv.z,
                        (va[i].w - ma) * ra * gv.w + bv.w);
        p2.x = pack_f16((vb[i].x - mb) * rb * gv.x + bv.x,
                        (vb[i].y - mb) * rb * gv.y + bv.y);
        p2.y = pack_f16((vb[i].z - mb) * rb * gv.z + bv.z,
                        (vb[i].w - mb) * rb * gv.w + bv.w);
        *(uint2*)(ha + idx) = p1;
        *(uint2*)(hb + idx) = p2;
    }
}

// ---------------------------------------------------------------------------
// W fp32 -> fp16 conversion (once per launch).
// ---------------------------------------------------------------------------
__global__ void wconv_kernel(const float* __restrict__ W) {
    int i = blockIdx.x * 256 + threadIdx.x;
    float4 v = *(const float4*)(W + (size_t)i * 4);
    uint2 p;
    p.x = pack_f16(v.x, v.y);
    p.y = pack_f16(v.z, v.w);
    *(uint2*)&g_wh[(size_t)i * 4] = p;
}

// ---------------------------------------------------------------------------
// QKV GEMM (unchanged from R16), pure fp16 mma.sync, triple-buffered cp.async.
// CTA tile 128x128, 8 warps (2m x 4n), warp tile 64x32, k-slab 32.
// Epilogue folds softmax scale (0.125*log2e) into the Q columns (n < 512).
// ---------------------------------------------------------------------------
#define GEMM_SMEM 56832  // 3 bufs x (As 10240 + Bs 8704)

__global__ void __launch_bounds__(256, 2) qkv_gemm_kernel(const float* __restrict__ bias) {
    extern __shared__ char gsm[];
    uint32_t gs = (uint32_t)__cvta_generic_to_shared(gsm);

    int t = threadIdx.x, lane = t & 31, wid = t >> 5;
    int g = lane >> 2, c = lane & 3;
    int grp = lane >> 3, r8 = lane & 7;
    int wm = (wid >> 2) * 64, wn = (wid & 3) * 32;
    int m0 = blockIdx.y * 128, n0 = blockIdx.x * 128;

    int arow_off = ((grp & 1) * 8 + r8) * 80 + (grp >> 1) * 16;
    const char* Ab = (const char*)g_xnh + (size_t)m0 * (CDIM * 2);
    const char* Bb = (const char*)g_wh + (size_t)n0 * 2;

    {
        #pragma unroll
        for (int j = 0; j < 2; j++) {
            int id = t + j * 256;
            int row = id >> 2, cc = id & 3;
            cp16(gs + row * 80 + cc * 16,
                 Ab + (size_t)row * (CDIM * 2) + cc * 16);
            int brow = id >> 4, bcc = id & 15;
            cp16(gs + 10240 + brow * 272 + bcc * 16,
                 Bb + (size_t)brow * (C3 * 2) + bcc * 16);
        }
        CP_COMMIT();
    }

    float acc[4][4][4] = {};
    int rbuf = 0;

    for (int s = 0; s < CDIM / 32; s++) {
        if (s + 1 < CDIM / 32) {
            int nbuf = (rbuf + 1 == 3) ? 0 : rbuf + 1;
            uint32_t bb = gs + nbuf * 18944;
            #pragma unroll
            for (int j = 0; j < 2; j++) {
                int id = t + j * 256;
                int row = id >> 2, cc = id & 3;
                cp16(bb + row * 80 + cc * 16,
                     Ab + (size_t)row * (CDIM * 2) + (s + 1) * 64 + cc * 16);
                int brow = id >> 4, bcc = id & 15;
                cp16(bb + 10240 + brow * 272 + bcc * 16,
                     Bb + (size_t)((s + 1) * 32 + brow) * (C3 * 2) + bcc * 16);
            }
        }
        CP_COMMIT();
        CP_WAIT1();
        __syncthreads();

        char* As = gsm + rbuf * 18944;
        char* Bs = As + 10240;

        #pragma unroll
        for (int kc = 0; kc < 2; kc++) {
            uint32_t af[4][4];
            #pragma unroll
            for (int mt = 0; mt < 4; mt++) {
                int ao = (wm + mt * 16) * 80 + kc * 32 + arow_off;
                ldmatrix_x4(af[mt][0], af[mt][1], af[mt][2], af[mt][3], As + ao);
            }
            #pragma unroll
            for (int ntp = 0; ntp < 2; ntp++) {
                int bo = (kc * 16 + (lane & 15)) * 272 + (wn + ntp * 16) * 2
                       + ((lane >> 4) << 4);
                uint32_t b0, b1, b2, b3;
                ldmatrix_x4_trans(b0, b1, b2, b3, Bs + bo);
                #pragma unroll
                for (int mt = 0; mt < 4; mt++) {
                    mma_f16(acc[mt][2*ntp],   af[mt], b0, b1);
                    mma_f16(acc[mt][2*ntp+1], af[mt], b2, b3);
                }
            }
        }
        rbuf = (rbuf + 1 == 3) ? 0 : rbuf + 1;
    }

    #pragma unroll
    for (int mt = 0; mt < 4; mt++) {
        int m = m0 + wm + mt * 16 + g;
        #pragma unroll
        for (int nt = 0; nt < 4; nt++) {
            int n = n0 + wn + nt * 8 + 2 * c;
            float sc = (n < CDIM) ? QK_LOG2_SCALE : 1.0f;
            float b0 = bias[n], b1 = bias[n + 1];
            #pragma unroll
            for (int rr = 0; rr < 2; rr++) {
                float s0 = (acc[mt][nt][2 * rr]     + b0) * sc;
                float s1 = (acc[mt][nt][2 * rr + 1] + b1) * sc;
                size_t off = (size_t)(m + 8 * rr) * C3 + n;
                *(uint32_t*)&g_qkvh[off] = pack_f16(s0, s1);
            }
        }
    }
}

// ---------------------------------------------------------------------------
// Flash attention (mainloop unchanged from R16): fp16 mma.sync, occupancy 2,
// ex2.approx.f16x2 on S fragments, triple-buffered cp.async K/V with
// wait_group(1) + one barrier per 64-kv iteration, HADD2 rs pre-sum +
// one ones-B MMA per mt per iteration. Epilogue now stores fp16.
// ---------------------------------------------------------------------------
#define ATTN_SMEM 92160  // Q 256x144 = 36864 + 3 bufs x (K 9216 + V 9216)
#define ONES_H2 0x3C003C00u

__global__ void __launch_bounds__(256, 2) attn_kernel() {
    extern __shared__ char dsm[];
    char* Qs = dsm;                        // 256 x 144 B
    char* KV = dsm + 36864;                // 3 bufs x [K, V] x (64 x 144)
    uint32_t kvs = (uint32_t)__cvta_generic_to_shared(KV);

    int t = threadIdx.x, lane = t & 31, wid = t >> 5;
    int g = lane >> 2, c = lane & 3;
    int grp = lane >> 3, r8 = lane & 7;
    int bh = blockIdx.y, b = bh >> 3, h = bh & 7;
    int m0 = blockIdx.x * 256;
    int wrow = wid * 32;

    const char* qkb = (const char*)g_qkvh;
    size_t qoff  = (size_t)(b * NSEQ + m0) * 3072 + h * 128;
    size_t kbase = (size_t)(b * NSEQ) * 3072 + 1024 + h * 128;
    size_t vbase = kbase + 1024;

    int frag_off = ((grp & 1) * 8 + r8) * 144 + (grp >> 1) * 16;  // K & Q ldmatrix
    int vrow_off = (lane & 15) * 144 + ((lane >> 4) << 4);        // V trans

    // --- prefetch KV chunk 0 into buffer 0 ---
    {
        #pragma unroll
        for (int j = 0; j < 2; j++) {
            int id = t + j * 256;
            int row = id >> 3, c16 = id & 7;
            size_t go = (size_t)row * 3072 + c16 * 16;
            uint32_t doff = row * 144 + c16 * 16;
            cp16(kvs + doff,        qkb + kbase + go);
            cp16(kvs + 9216 + doff, qkb + vbase + go);
        }
        CP_COMMIT();
    }

    // --- stage Q (256 rows x 128 B), 8 threads/row, coalesced ---
    {
        #pragma unroll
        for (int j = 0; j < 8; j++) {
            int id = t + j * 256;
            int row = id >> 3, c16 = id & 7;
            size_t so = qoff + (size_t)row * 3072 + c16 * 16;
            *(uint4*)(Qs + row * 144 + c16 * 16) = *(const uint4*)(qkb + so);
        }
    }

    float oacc[2][8][4] = {};
    float rsacc[2][4] = {};
    int rbuf = 0;

    for (int it = 0; it < NSEQ / 64; it++) {
        if (it + 1 < NSEQ / 64) {
            int nbuf = (rbuf + 1 == 3) ? 0 : rbuf + 1;
            uint32_t bb = kvs + nbuf * 18432;
            #pragma unroll
            for (int j = 0; j < 2; j++) {
                int id = t + j * 256;
                int row = id >> 3, c16 = id & 7;
                size_t go = (size_t)((it + 1) * 64 + row) * 3072 + c16 * 16;
                uint32_t doff = row * 144 + c16 * 16;
                cp16(bb + doff,        qkb + kbase + go);
                cp16(bb + 9216 + doff, qkb + vbase + go);
            }
        }
        CP_COMMIT();
        CP_WAIT1();
        __syncthreads();   // single barrier per iteration

        char* Kp = KV + rbuf * 18432;
        char* Vp = Kp + 9216;

        // S = Q K^T, single fp16 chain over k=64.
        uint32_t S[4][2][4] = {};
        #pragma unroll
        for (int kc = 0; kc < 4; kc++) {
            uint32_t q0[4], q1[4];
            ldmatrix_x4(q0[0], q0[1], q0[2], q0[3],
                        Qs + wrow * 144 + kc * 32 + frag_off);
            ldmatrix_x4(q1[0], q1[1], q1[2], q1[3],
                        Qs + (wrow + 16) * 144 + kc * 32 + frag_off);
            #pragma unroll
            for (int np = 0; np < 4; np++) {
                uint32_t k0, k1, k2, k3;
                ldmatrix_x4(k0, k1, k2, k3, Kp + np * 2304 + kc * 32 + frag_off);
                mma_f16_h(&S[np][0][0], q0, k0, k2);
                mma_f16_h(&S[np][0][2], q0, k1, k3);
                mma_f16_h(&S[np][1][0], q1, k0, k2);
                mma_f16_h(&S[np][1][2], q1, k1, k3);
            }
        }

        // Softmax + O per np; accumulate P in fp16 for row sums.
        uint32_t psum[2][4] = {};
        #pragma unroll
        for (int np = 0; np < 4; np++) {
            uint32_t pfr[2][4];
            #pragma unroll
            for (int mt = 0; mt < 2; mt++) {
                H2EXP2(pfr[mt][0], S[np][mt][0]);
                H2EXP2(pfr[mt][1], S[np][mt][1]);
                H2EXP2(pfr[mt][2], S[np][mt][2]);
                H2EXP2(pfr[mt][3], S[np][mt][3]);
                HADD2(psum[mt][0], pfr[mt][0]);
                HADD2(psum[mt][1], pfr[mt][1]);
                HADD2(psum[mt][2], pfr[mt][2]);
                HADD2(psum[mt][3], pfr[mt][3]);
            }
            #pragma unroll
            for (int dt = 0; dt < 4; dt++) {
                int vo = np * 16 * 144 + dt * 32 + vrow_off;
                uint32_t h0, h1, h2, h3;
                ldmatrix_x4_trans(h0, h1, h2, h3, Vp + vo);
                #pragma unroll
                for (int mt = 0; mt < 2; mt++) {
                    mma_f16(oacc[mt][2*dt],     pfr[mt], h0, h1);
                    mma_f16(oacc[mt][2*dt + 1], pfr[mt], h2, h3);
                }
            }
        }
        // row sums: one ones-B MMA per mt per iteration (MMA linear in A)
        #pragma unroll
        for (int mt = 0; mt < 2; mt++)
            mma_f16(rsacc[mt], psum[mt], ONES_H2, ONES_H2);

        rbuf = (rbuf + 1 == 3) ? 0 : rbuf + 1;
    }

    // Normalize and store fp16 (rsacc[mt][0]=row g, rsacc[mt][2]=row g+8)
    #pragma unroll
    for (int mt = 0; mt < 2; mt++) {
        float inv0 = 1.f / rsacc[mt][0];
        float inv1 = 1.f / rsacc[mt][2];

        __half* o0 = g_valh + (size_t)(b * NSEQ + m0 + wrow + mt * 16 + g) * CDIM
                   + h * HD + 2 * c;
        __half* o1 = o0 + (size_t)8 * CDIM;
        #pragma unroll
        for (int n = 0; n < 8; n++) {
            *(uint32_t*)(o0 + n * 8) = pack_f16(oacc[mt][n][0] * inv0,
                                                oacc[mt][n][1] * inv0);
            *(uint32_t*)(o1 + n * 8) = pack_f16(oacc[mt][n][2] * inv1,
                                                oacc[mt][n][3] * inv1);
        }
    }
}

// ---------------------------------------------------------------------------
// Post-LayerNorm + residual, 2 rows per warp; reads fp16 val + fp16 xn:
// out = xn + LN(val)*g + beta (fp32 math, fp32 output).
// Grid: NROWS/16 blocks x 256 threads.
// ---------------------------------------------------------------------------
__global__ void post_ln_kernel(const float* __restrict__ g,
                               const float* __restrict__ beta,
                               float* __restrict__ out) {
    int wid = threadIdx.x >> 5, lane = threadIdx.x & 31;
    int rowa = blockIdx.x * 16 + wid * 2;
    int rowb = rowa + 1;
    const __half* va_p = g_valh + (size_t)rowa * CDIM;
    const __half* vb_p = g_valh + (size_t)rowb * CDIM;
    // 512 halves/row; each lane handles 16 (4x uint2 per row)
    float2 va[8], vb[8];
    #pragma unroll
    for (int i = 0; i < 4; i++) {
        uint2 ua = *(const uint2*)(va_p + (lane + i * 32) * 4);
        uint2 ub = *(const uint2*)(vb_p + (lane + i * 32) * 4);
        va[2*i]     = __half22float2(*(__half2*)&ua.x);
        va[2*i + 1] = __half22float2(*(__half2*)&ua.y);
        vb[2*i]     = __half22float2(*(__half2*)&ub.x);
        vb[2*i + 1] = __half22float2(*(__half2*)&ub.y);
    }
    float sa = 0.f, sa2 = 0.f, sb = 0.f, sb2 = 0.f;
    #pragma unroll
    for (int i = 0; i < 8; i++) {
        sa  += va[i].x + va[i].y;
        sa2 += va[i].x * va[i].x + va[i].y * va[i].y;
        sb  += vb[i].x + vb[i].y;
        sb2 += vb[i].x * vb[i].x + vb[i].y * vb[i].y;
    }
    #pragma unroll
    for (int o = 16; o > 0; o >>= 1) {
        sa  += __shfl_xor_sync(0xffffffffu, sa,  o);
        sa2 += __shfl_xor_sync(0xffffffffu, sa2, o);
        sb  += __shfl_xor_sync(0xffffffffu, sb,  o);
        sb2 += __shfl_xor_sync(0xffffffffu, sb2, o);
    }
    float ma = sa * (1.f / CDIM), mb = sb * (1.f / CDIM);
    float ra = rsqrtf(sa2 * (1.f / CDIM) - ma * ma + 1e-5f);
    float rb = rsqrtf(sb2 * (1.f / CDIM) - mb * mb + 1e-5f);
    const __half* xa = g_xnh + (size_t)rowa * CDIM;
    const __half* xb = g_xnh + (size_t)rowb * CDIM;
    float* oa = out + (size_t)rowa * CDIM;
    float* ob = out + (size_t)rowb * CDIM;
    #pragma unroll
    for (int i = 0; i < 4; i++) {
        int idx = (lane + i * 32) * 4;
        float4 gv = *(const float4*)(g + idx);
        float4 bv = *(const float4*)(beta + idx);
        uint2 uxa = *(const uint2*)(xa + idx);
        uint2 uxb = *(const uint2*)(xb + idx);
        float2 x1l = __half22float2(*(__half2*)&uxa.x);
        float2 x1h = __half22float2(*(__half2*)&uxa.y);
        float2 x2l = __half22float2(*(__half2*)&uxb.x);
        float2 x2h = __half22float2(*(__half2*)&uxb.y);
        float4 o1, o2;
        o1.x = x1l.x + (va[2*i].x   - ma) * ra * gv.x + bv.x;
        o1.y = x1l.y + (va[2*i].y   - ma) * ra * gv.y + bv.y;
        o1.z = x1h.x + (va[2*i+1].x - ma) * ra * gv.z + bv.z;
        o1.w = x1h.y + (va[2*i+1].y - ma) * ra * gv.w + bv.w;
        o2.x = x2l.x + (vb[2*i].x   - mb) * rb * gv.x + bv.x;
        o2.y = x2l.y + (vb[2*i].y   - mb) * rb * gv.y + bv.y;
        o2.z = x2h.x + (vb[2*i+1].x - mb) * rb * gv.z + bv.z;
        o2.w = x2h.y + (vb[2*i+1].y - mb) * rb * gv.w + bv.w;
        *(float4*)(oa + idx) = o1;
        *(float4*)(ob + idx) = o2;
    }
}

// ---------------------------------------------------------------------------
extern "C" void kernel_launch(void* const* d_in, const int* in_sizes, int n_in,
                              void* d_out, int out_size) {
    const float* x     = (const float*)d_in[0];
    const float* w_qkv = (const float*)d_in[1];
    const float* b_qkv = (const float*)d_in[2];
    const float* g_pre = (const float*)d_in[3];
    const float* beta_pre  = (const float*)d_in[4];
    const float* g_post    = (const float*)d_in[5];
    const float* beta_post = (const float*)d_in[6];
    float* out = (float*)d_out;

    (void)in_sizes; (void)n_in; (void)out_size;

    cudaFuncSetAttribute(attn_kernel,
                         cudaFuncAttributeMaxDynamicSharedMemorySize, ATTN_SMEM);
    cudaFuncSetAttribute(attn_kernel,
                         cudaFuncAttributePreferredSharedMemoryCarveout, 100);
    cudaFuncSetAttribute(qkv_gemm_kernel,
                         cudaFuncAttributeMaxDynamicSharedMemorySize, GEMM_SMEM);

    wconv_kernel<<<(CDIM * C3) / 1024, 256>>>(w_qkv);
    pre_ln_kernel<<<NROWS / 16, 256>>>(x, g_pre, beta_pre);

    dim3 ggrid(C3 / 128, NROWS / 128);
    qkv_gemm_kernel<<<ggrid, 256, GEMM_SMEM>>>(b_qkv);

    dim3 agrid(NSEQ / 256, BATCH * NH);
    attn_kernel<<<agrid, 256, ATTN_SMEM>>>();

    post_ln_kernel<<<NROWS / 16, 256>>>(g_post, beta_post, out);
}